// round 16
// baseline (speedup 1.0000x reference)
#include <cuda_runtime.h>
#include <math.h>

#define NG    2048
#define W     128
#define H     128
#define EPSV  1e-4f
#define NEARV 0.3f
#define TAU   8.0f        // cull threshold on folded exponent

// prepsort: 64 blocks x 1024 threads (32 warps = 32 gaussians ranked per block)
#define PBT   1024
#define GPB   32

// render: 8x8 px tiles, 256 blocks x 1024 threads, 16 depth chunks
#define RTW   8
#define RTH   8
#define RPPT  (RTW*RTH)    // 64 px
#define RNSUB 16           // depth chunks
#define RBT   (RNSUB*RPPT) // 1024 threads
#define NTX   (W/RTW)      // 16
#define NTY   (H/RTH)      // 16
#define NCAP  1024         // staged survivor cap

// ---------------- device scratch (all arrays in depth-sorted order) -------------
__device__ float4 d_sga[NG];   // u, v, A, B
__device__ float4 d_sgb[NG];   // C, L, r, g
__device__ float4 d_scu[NG];   // u, v, hx, hy
__device__ float  d_sbb[NG];   // b

__device__ __forceinline__ float sigmoidf_(float x) {
    return 1.0f / (1.0f + expf(-x));
}

// ---------------- 1) fused prep + global stable depth-sort ----------------
__global__ void __launch_bounds__(PBT) prepsort_kernel(
        const float* __restrict__ pos,
        const float* __restrict__ rgb,
        const float* __restrict__ opa,
        const float* __restrict__ quat,
        const float* __restrict__ scale,
        const float* __restrict__ rot,
        const float* __restrict__ tran)
{
    __shared__ float sk[NG];       // all 2048 depth keys
    __shared__ int   srank[GPB];   // ranks of this block's 32 gaussians

    const int t    = threadIdx.x;
    const int wid  = t >> 5, lane = t & 31;
    const int bid  = blockIdx.x;

    float Rw[9];
#pragma unroll
    for (int i = 0; i < 9; i++) Rw[i] = __ldg(&rot[i]);
    const float t0 = __ldg(&tran[0]), t1 = __ldg(&tran[1]), t2 = __ldg(&tran[2]);

    // ---- phase A: all 2048 depth keys (redundant per block; keys are cheap) ----
#pragma unroll
    for (int n = t; n < NG; n += PBT) {
        float p0 = __ldg(&pos[n*3+0]), p1 = __ldg(&pos[n*3+1]), p2 = __ldg(&pos[n*3+2]);
        float x = Rw[0]*p0 + Rw[1]*p1 + Rw[2]*p2 + t0;
        float y = Rw[3]*p0 + Rw[4]*p1 + Rw[5]*p2 + t1;
        float z = Rw[6]*p0 + Rw[7]*p1 + Rw[8]*p2 + t2;
        sk[n] = sqrtf(x*x + y*y + z*z);
    }
    __syncthreads();

    // ---- phase B: warp w ranks gaussian g = bid*32 + w (stable) ----
    {
        const int g = bid * GPB + wid;
        float ki = sk[g];
        int c = 0;
#pragma unroll 8
        for (int j = lane; j < NG; j += 32) {          // 64 iters, uniform
            float kj = sk[j];
            c += (int)((kj < ki) | ((kj == ki) & (j < g)));
        }
#pragma unroll
        for (int o = 16; o; o >>= 1) c += __shfl_xor_sync(0xFFFFFFFFu, c, o);
        if (lane == 0) srank[wid] = c;
    }
    __syncthreads();

    // ---- phase C: threads 0..31 prep the block's 32 gaussians, scatter sorted ----
    if (t < GPB) {
        const int n = bid * GPB + t;
        const int rk = srank[t];

        float p0 = __ldg(&pos[n*3+0]), p1 = __ldg(&pos[n*3+1]), p2 = __ldg(&pos[n*3+2]);
        float x = Rw[0]*p0 + Rw[1]*p1 + Rw[2]*p2 + t0;
        float y = Rw[3]*p0 + Rw[4]*p1 + Rw[5]*p2 + t1;
        float z = Rw[6]*p0 + Rw[7]*p1 + Rw[8]*p2 + t2;

        float iz  = 1.0f / z;
        float u = x * iz, v = y * iz;
        float iz2 = iz * iz;

        float M00 = iz*Rw[0] - x*iz2*Rw[6];
        float M01 = iz*Rw[1] - x*iz2*Rw[7];
        float M02 = iz*Rw[2] - x*iz2*Rw[8];
        float M10 = iz*Rw[3] - y*iz2*Rw[6];
        float M11 = iz*Rw[4] - y*iz2*Rw[7];
        float M12 = iz*Rw[5] - y*iz2*Rw[8];

        float4 q4 = __ldg((const float4*)(quat + n*4));
        float qw = q4.x, qx = q4.y, qy = q4.z, qz = q4.w;
        float qn = rsqrtf(qw*qw + qx*qx + qy*qy + qz*qz);
        qw *= qn; qx *= qn; qy *= qn; qz *= qn;
        float R00 = 1.0f - 2.0f*(qy*qy + qz*qz);
        float R01 = 2.0f*(qx*qy - qw*qz);
        float R02 = 2.0f*(qx*qz + qw*qy);
        float R10 = 2.0f*(qx*qy + qw*qz);
        float R11 = 1.0f - 2.0f*(qx*qx + qz*qz);
        float R12 = 2.0f*(qy*qz - qw*qx);
        float R20 = 2.0f*(qx*qz - qw*qy);
        float R21 = 2.0f*(qy*qz + qw*qx);
        float R22 = 1.0f - 2.0f*(qx*qx + qy*qy);

        float s0 = fabsf(__ldg(&scale[n*3+0])) + 1e-4f;
        float s1 = fabsf(__ldg(&scale[n*3+1])) + 1e-4f;
        float s2 = fabsf(__ldg(&scale[n*3+2])) + 1e-4f;
        float q0 = s0*s0, q1 = s1*s1, q2 = s2*s2;

        float c00 = R00*R00*q0 + R01*R01*q1 + R02*R02*q2;
        float c01 = R00*R10*q0 + R01*R11*q1 + R02*R12*q2;
        float c02 = R00*R20*q0 + R01*R21*q1 + R02*R22*q2;
        float c11 = R10*R10*q0 + R11*R11*q1 + R12*R12*q2;
        float c12 = R10*R20*q0 + R11*R21*q1 + R12*R22*q2;
        float c22 = R20*R20*q0 + R21*R21*q1 + R22*R22*q2;

        float v00 = c00*M00 + c01*M01 + c02*M02;
        float v01 = c01*M00 + c11*M01 + c12*M02;
        float v02 = c02*M00 + c12*M01 + c22*M02;
        float v10 = c00*M10 + c01*M11 + c02*M12;
        float v11 = c01*M10 + c11*M11 + c12*M12;
        float v12 = c02*M10 + c12*M11 + c22*M12;

        float a  = M00*v00 + M01*v01 + M02*v02 + EPSV;   // Sigma_xx
        float b  = M00*v10 + M01*v11 + M02*v12;
        float cc = M10*v10 + M11*v11 + M12*v12 + EPSV;   // Sigma_yy

        float det  = a*cc - b*b;
        float idet = 1.0f / det;
        float A = -0.5f * cc * idet;
        float B =  b * idet;
        float C = -0.5f * a  * idet;

        float opa_s = sigmoidf_(__ldg(&opa[n]));
        float L = (z > NEARV) ? logf(opa_s) : -1e30f;

        float tau = TAU + L;
        float hx, hy;
        if (tau > 0.0f) {
            hx = sqrtf(2.0f * tau * a);
            hy = sqrtf(2.0f * tau * cc);
        } else {
            hx = -1e30f; hy = -1e30f;   // always culled
        }

        float cr = sigmoidf_(__ldg(&rgb[n*3+0]));
        float cg = sigmoidf_(__ldg(&rgb[n*3+1]));
        float cb = sigmoidf_(__ldg(&rgb[n*3+2]));

        d_scu[rk] = make_float4(u, v, hx, hy);
        d_sga[rk] = make_float4(u, v, A, B);
        d_sgb[rk] = make_float4(C, L, cr, cg);
        d_sbb[rk] = cb;
    }
}

// ---------------- 2) per-tile ordered compaction + composite ----------------
extern __shared__ char smx[];
// sga 16K | sgb 16K | sbb 4K | part 16K = 52KB
#define O_SGA  0
#define O_SGB  (O_SGA + NCAP*16)
#define O_SBB  (O_SGB + NCAP*16)
#define O_PART (O_SBB + NCAP*4)
#define RSMEM  (O_PART + RNSUB*RPPT*16)   // 53248 B

__global__ void __launch_bounds__(RBT) render_kernel(float* __restrict__ out)
{
    float4* sga  = (float4*)(smx + O_SGA);
    float4* sgb  = (float4*)(smx + O_SGB);
    float*  sbb  = (float* )(smx + O_SBB);
    float4* part = (float4*)(smx + O_PART);
    __shared__ int warpcnt[32];

    const int t    = threadIdx.x;
    const int wid  = t >> 5, lane = t & 31;
    const int tx   = blockIdx.x, ty = blockIdx.y;

    const float xmin = (tx*RTW         - 63.5f) * (1.0f/128.0f);
    const float xmax = (tx*RTW + RTW-1 - 63.5f) * (1.0f/128.0f);
    const float ymin = (ty*RTH         - 63.5f) * (1.0f/128.0f);
    const float ymax = (ty*RTH + RTH-1 - 63.5f) * (1.0f/128.0f);

    // ---- order-preserving compaction of globally sorted list + fused staging ----
    int base = 0;
#pragma unroll
    for (int p = 0; p < NG/RBT; p++) {             // 2 passes, uniform
        int i = p*RBT + t;
        float4 cv = __ldg(&d_scu[i]);
        bool keep = (cv.x - cv.z <= xmax) && (cv.x + cv.z >= xmin) &&
                    (cv.y - cv.w <= ymax) && (cv.y + cv.w >= ymin);
        unsigned m = __ballot_sync(0xFFFFFFFFu, keep);
        int wofs = __popc(m & ((1u << lane) - 1u));
        if (lane == 0) warpcnt[wid] = __popc(m);
        __syncthreads();
        if (t < 32) {                               // warp 0, full mask
            int v = warpcnt[t];
#pragma unroll
            for (int o = 1; o < 32; o <<= 1) {
                int u2 = __shfl_up_sync(0xFFFFFFFFu, v, o);
                if (lane >= o) v += u2;
            }
            warpcnt[t] = v;                         // inclusive scan
        }
        __syncthreads();
        int slot = base + (wid ? warpcnt[wid-1] : 0) + wofs;
        if (keep && slot < NCAP) {
            sga[slot] = __ldg(&d_sga[i]);
            sgb[slot] = __ldg(&d_sgb[i]);
            sbb[slot] = __ldg(&d_sbb[i]);
        }
        base += warpcnt[31];
        __syncthreads();
    }
    const int N = (base < NCAP) ? base : NCAP;

    // ---- chunked branch-free composite ----
    const int sub = t >> 6;             // 0..15
    const int pix = t & (RPPT-1);       // 0..63
    const int x = tx*RTW + (pix & (RTW-1));
    const int y = ty*RTH + (pix >> 3);
    const float px = (x - 63.5f) * (1.0f/128.0f);
    const float py = (y - 63.5f) * (1.0f/128.0f);

    const int Nc = (N + RNSUB - 1) / RNSUB;
    const int k0 = sub * Nc;
    int k1 = k0 + Nc; if (k1 > N) k1 = N;

    float T = 1.0f, cr = 0.0f, cg = 0.0f, cb = 0.0f;
#pragma unroll 4
    for (int k = k0; k < k1; k++) {
        float4 ga = sga[k];
        float4 gb = sgb[k];
        float dx = px - ga.x;
        float dy = py - ga.y;
        float pw = fmaf(fmaf(ga.z, dx, ga.w * dy), dx, fmaf(gb.x * dy, dy, gb.y));
        float al = fminf(__expf(pw), 0.99f);
        float wg = T * al;
        cr = fmaf(wg, gb.z, cr);
        cg = fmaf(wg, gb.w, cg);
        cb = fmaf(wg, sbb[k], cb);
        T -= wg;
    }
    part[sub * RPPT + pix] = make_float4(cr, cg, cb, T);
    __syncthreads();

    // ---- exact recombination + store ----
    if (t < RPPT) {
        float P = 1.0f, r = 0.0f, g = 0.0f, b = 0.0f;
#pragma unroll
        for (int s = 0; s < RNSUB; s++) {
            float4 qq = part[s * RPPT + t];
            r = fmaf(P, qq.x, r);
            g = fmaf(P, qq.y, g);
            b = fmaf(P, qq.z, b);
            P *= qq.w;
        }
        int xx = tx*RTW + (t & (RTW-1));
        int yy = ty*RTH + (t >> 3);
        int o = (yy * W + xx) * 3;
        out[o + 0] = r;
        out[o + 1] = g;
        out[o + 2] = b;
    }
}

extern "C" void kernel_launch(void* const* d_in, const int* in_sizes, int n_in,
                              void* d_out, int out_size)
{
    const float* pos   = (const float*)d_in[0];
    const float* rgb   = (const float*)d_in[1];
    const float* opa   = (const float*)d_in[2];
    const float* quat  = (const float*)d_in[3];
    const float* scale = (const float*)d_in[4];
    const float* rot   = (const float*)d_in[5];
    const float* tran  = (const float*)d_in[6];
    float* out = (float*)d_out;

    static int smem_set = 0;
    if (!smem_set) {
        cudaFuncSetAttribute(render_kernel,
                             cudaFuncAttributeMaxDynamicSharedMemorySize,
                             RSMEM);
        smem_set = 1;
    }

    prepsort_kernel<<<NG/GPB, PBT>>>(pos, rgb, opa, quat, scale, rot, tran);
    render_kernel<<<dim3(NTX, NTY), RBT, RSMEM>>>(out);
}

// round 17
// speedup vs baseline: 1.1577x; 1.1577x over previous
#include <cuda_runtime.h>
#include <math.h>

#define NG    2048
#define W     128
#define H     128
#define EPSV  1e-4f
#define NEARV 0.3f
#define TAU   8.0f        // cull threshold on folded exponent

// prepsort: 128 blocks x 512 threads; 16 gaussians per block (1 per warp)
#define PNB   128
#define PBT   512
#define GPB   (NG/PNB)    // 16

// render: 8x8 px tiles, 256 blocks x 1024 threads, 16 depth chunks
#define RTW   8
#define RTH   8
#define RPPT  (RTW*RTH)    // 64 px
#define RNSUB 16           // depth chunks
#define RBT   (RNSUB*RPPT) // 1024 threads
#define NTX   (W/RTW)      // 16
#define NTY   (H/RTH)      // 16
#define NCAP  1024         // staged survivor cap

// ---------------- device scratch (all arrays in depth-sorted order) -------------
__device__ float4 d_sga[NG];   // u, v, A, B
__device__ float4 d_sgb[NG];   // C, L, r, g
__device__ float4 d_scu[NG];   // u, v, hx, hy
__device__ float  d_sbb[NG];   // b

__device__ __forceinline__ float sigmoidf_(float x) {
    return 1.0f / (1.0f + expf(-x));
}

// ---------------- 1) fused prep + global stable depth-sort ----------------
__global__ void __launch_bounds__(PBT) prepsort_kernel(
        const float* __restrict__ pos,
        const float* __restrict__ rgb,
        const float* __restrict__ opa,
        const float* __restrict__ quat,
        const float* __restrict__ scale,
        const float* __restrict__ rot,
        const float* __restrict__ tran)
{
    __shared__ float sk[NG];       // all 2048 depth keys
    __shared__ int   srank[GPB];   // ranks of this block's 16 gaussians

    const int t    = threadIdx.x;
    const int wid  = t >> 5, lane = t & 31;
    const int bid  = blockIdx.x;

    float Rw[9];
#pragma unroll
    for (int i = 0; i < 9; i++) Rw[i] = __ldg(&rot[i]);
    const float t0 = __ldg(&tran[0]), t1 = __ldg(&tran[1]), t2 = __ldg(&tran[2]);

    // ---- phase A: all 2048 depth keys (redundant per block; cheap) ----
#pragma unroll
    for (int n = t; n < NG; n += PBT) {
        float p0 = __ldg(&pos[n*3+0]), p1 = __ldg(&pos[n*3+1]), p2 = __ldg(&pos[n*3+2]);
        float x = Rw[0]*p0 + Rw[1]*p1 + Rw[2]*p2 + t0;
        float y = Rw[3]*p0 + Rw[4]*p1 + Rw[5]*p2 + t1;
        float z = Rw[6]*p0 + Rw[7]*p1 + Rw[8]*p2 + t2;
        sk[n] = sqrtf(x*x + y*y + z*z);
    }
    __syncthreads();

    // ---- phase B: warp w ranks gaussian g = bid*16 + w (all 16 warps busy) ----
    {
        const int g = bid * GPB + wid;
        float ki = sk[g];
        int c = 0;
#pragma unroll 8
        for (int j = lane; j < NG; j += 32) {          // 64 iters, uniform
            float kj = sk[j];
            c += (int)((kj < ki) | ((kj == ki) & (j < g)));
        }
#pragma unroll
        for (int o = 16; o; o >>= 1) c += __shfl_xor_sync(0xFFFFFFFFu, c, o);
        if (lane == 0) srank[wid] = c;
    }
    __syncthreads();

    // ---- phase C: threads 0..15 prep the block's 16 gaussians, scatter sorted ----
    // (2048 threads chip-wide doing prep concurrently across 128 blocks)
    if (t < GPB) {
        const int n = bid * GPB + t;
        const int rk = srank[t];

        float p0 = __ldg(&pos[n*3+0]), p1 = __ldg(&pos[n*3+1]), p2 = __ldg(&pos[n*3+2]);
        float x = Rw[0]*p0 + Rw[1]*p1 + Rw[2]*p2 + t0;
        float y = Rw[3]*p0 + Rw[4]*p1 + Rw[5]*p2 + t1;
        float z = Rw[6]*p0 + Rw[7]*p1 + Rw[8]*p2 + t2;

        float iz  = 1.0f / z;
        float u = x * iz, v = y * iz;
        float iz2 = iz * iz;

        float M00 = iz*Rw[0] - x*iz2*Rw[6];
        float M01 = iz*Rw[1] - x*iz2*Rw[7];
        float M02 = iz*Rw[2] - x*iz2*Rw[8];
        float M10 = iz*Rw[3] - y*iz2*Rw[6];
        float M11 = iz*Rw[4] - y*iz2*Rw[7];
        float M12 = iz*Rw[5] - y*iz2*Rw[8];

        float4 q4 = __ldg((const float4*)(quat + n*4));
        float qw = q4.x, qx = q4.y, qy = q4.z, qz = q4.w;
        float qn = rsqrtf(qw*qw + qx*qx + qy*qy + qz*qz);
        qw *= qn; qx *= qn; qy *= qn; qz *= qn;
        float R00 = 1.0f - 2.0f*(qy*qy + qz*qz);
        float R01 = 2.0f*(qx*qy - qw*qz);
        float R02 = 2.0f*(qx*qz + qw*qy);
        float R10 = 2.0f*(qx*qy + qw*qz);
        float R11 = 1.0f - 2.0f*(qx*qx + qz*qz);
        float R12 = 2.0f*(qy*qz - qw*qx);
        float R20 = 2.0f*(qx*qz - qw*qy);
        float R21 = 2.0f*(qy*qz + qw*qx);
        float R22 = 1.0f - 2.0f*(qx*qx + qy*qy);

        float s0 = fabsf(__ldg(&scale[n*3+0])) + 1e-4f;
        float s1 = fabsf(__ldg(&scale[n*3+1])) + 1e-4f;
        float s2 = fabsf(__ldg(&scale[n*3+2])) + 1e-4f;
        float q0 = s0*s0, q1 = s1*s1, q2 = s2*s2;

        float c00 = R00*R00*q0 + R01*R01*q1 + R02*R02*q2;
        float c01 = R00*R10*q0 + R01*R11*q1 + R02*R12*q2;
        float c02 = R00*R20*q0 + R01*R21*q1 + R02*R22*q2;
        float c11 = R10*R10*q0 + R11*R11*q1 + R12*R12*q2;
        float c12 = R10*R20*q0 + R11*R21*q1 + R12*R22*q2;
        float c22 = R20*R20*q0 + R21*R21*q1 + R22*R22*q2;

        float v00 = c00*M00 + c01*M01 + c02*M02;
        float v01 = c01*M00 + c11*M01 + c12*M02;
        float v02 = c02*M00 + c12*M01 + c22*M02;
        float v10 = c00*M10 + c01*M11 + c02*M12;
        float v11 = c01*M10 + c11*M11 + c12*M12;
        float v12 = c02*M10 + c12*M11 + c22*M12;

        float a  = M00*v00 + M01*v01 + M02*v02 + EPSV;   // Sigma_xx
        float b  = M00*v10 + M01*v11 + M02*v12;
        float cc = M10*v10 + M11*v11 + M12*v12 + EPSV;   // Sigma_yy

        float det  = a*cc - b*b;
        float idet = 1.0f / det;
        float A = -0.5f * cc * idet;
        float B =  b * idet;
        float C = -0.5f * a  * idet;

        float opa_s = sigmoidf_(__ldg(&opa[n]));
        float L = (z > NEARV) ? logf(opa_s) : -1e30f;

        float tau = TAU + L;
        float hx, hy;
        if (tau > 0.0f) {
            hx = sqrtf(2.0f * tau * a);
            hy = sqrtf(2.0f * tau * cc);
        } else {
            hx = -1e30f; hy = -1e30f;   // always culled
        }

        float cr = sigmoidf_(__ldg(&rgb[n*3+0]));
        float cg = sigmoidf_(__ldg(&rgb[n*3+1]));
        float cb = sigmoidf_(__ldg(&rgb[n*3+2]));

        d_scu[rk] = make_float4(u, v, hx, hy);
        d_sga[rk] = make_float4(u, v, A, B);
        d_sgb[rk] = make_float4(C, L, cr, cg);
        d_sbb[rk] = cb;
    }
}

// ---------------- 2) per-tile ordered compaction + composite ----------------
extern __shared__ char smx[];
// sga 16K | sgb 16K | sbb 4K | part 16K = 52KB
#define O_SGA  0
#define O_SGB  (O_SGA + NCAP*16)
#define O_SBB  (O_SGB + NCAP*16)
#define O_PART (O_SBB + NCAP*4)
#define RSMEM  (O_PART + RNSUB*RPPT*16)   // 53248 B

__global__ void __launch_bounds__(RBT) render_kernel(float* __restrict__ out)
{
    float4* sga  = (float4*)(smx + O_SGA);
    float4* sgb  = (float4*)(smx + O_SGB);
    float*  sbb  = (float* )(smx + O_SBB);
    float4* part = (float4*)(smx + O_PART);
    __shared__ int warpcnt[32];

    const int t    = threadIdx.x;
    const int wid  = t >> 5, lane = t & 31;
    const int tx   = blockIdx.x, ty = blockIdx.y;

    const float xmin = (tx*RTW         - 63.5f) * (1.0f/128.0f);
    const float xmax = (tx*RTW + RTW-1 - 63.5f) * (1.0f/128.0f);
    const float ymin = (ty*RTH         - 63.5f) * (1.0f/128.0f);
    const float ymax = (ty*RTH + RTH-1 - 63.5f) * (1.0f/128.0f);

    // ---- order-preserving compaction of globally sorted list + fused staging ----
    int base = 0;
#pragma unroll
    for (int p = 0; p < NG/RBT; p++) {             // 2 passes, uniform
        int i = p*RBT + t;
        float4 cv = __ldg(&d_scu[i]);
        bool keep = (cv.x - cv.z <= xmax) && (cv.x + cv.z >= xmin) &&
                    (cv.y - cv.w <= ymax) && (cv.y + cv.w >= ymin);
        unsigned m = __ballot_sync(0xFFFFFFFFu, keep);
        int wofs = __popc(m & ((1u << lane) - 1u));
        if (lane == 0) warpcnt[wid] = __popc(m);
        __syncthreads();
        if (t < 32) {                               // warp 0, full mask
            int v = warpcnt[t];
#pragma unroll
            for (int o = 1; o < 32; o <<= 1) {
                int u2 = __shfl_up_sync(0xFFFFFFFFu, v, o);
                if (lane >= o) v += u2;
            }
            warpcnt[t] = v;                         // inclusive scan
        }
        __syncthreads();
        int slot = base + (wid ? warpcnt[wid-1] : 0) + wofs;
        if (keep && slot < NCAP) {
            sga[slot] = __ldg(&d_sga[i]);
            sgb[slot] = __ldg(&d_sgb[i]);
            sbb[slot] = __ldg(&d_sbb[i]);
        }
        base += warpcnt[31];
        __syncthreads();
    }
    const int N = (base < NCAP) ? base : NCAP;

    // ---- chunked branch-free composite ----
    const int sub = t >> 6;             // 0..15
    const int pix = t & (RPPT-1);       // 0..63
    const int x = tx*RTW + (pix & (RTW-1));
    const int y = ty*RTH + (pix >> 3);
    const float px = (x - 63.5f) * (1.0f/128.0f);
    const float py = (y - 63.5f) * (1.0f/128.0f);

    const int Nc = (N + RNSUB - 1) / RNSUB;
    const int k0 = sub * Nc;
    int k1 = k0 + Nc; if (k1 > N) k1 = N;

    float T = 1.0f, cr = 0.0f, cg = 0.0f, cb = 0.0f;
#pragma unroll 4
    for (int k = k0; k < k1; k++) {
        float4 ga = sga[k];
        float4 gb = sgb[k];
        float dx = px - ga.x;
        float dy = py - ga.y;
        float pw = fmaf(fmaf(ga.z, dx, ga.w * dy), dx, fmaf(gb.x * dy, dy, gb.y));
        float al = fminf(__expf(pw), 0.99f);
        float wg = T * al;
        cr = fmaf(wg, gb.z, cr);
        cg = fmaf(wg, gb.w, cg);
        cb = fmaf(wg, sbb[k], cb);
        T -= wg;
    }
    part[sub * RPPT + pix] = make_float4(cr, cg, cb, T);
    __syncthreads();

    // ---- exact recombination + store ----
    if (t < RPPT) {
        float P = 1.0f, r = 0.0f, g = 0.0f, b = 0.0f;
#pragma unroll
        for (int s = 0; s < RNSUB; s++) {
            float4 qq = part[s * RPPT + t];
            r = fmaf(P, qq.x, r);
            g = fmaf(P, qq.y, g);
            b = fmaf(P, qq.z, b);
            P *= qq.w;
        }
        int xx = tx*RTW + (t & (RTW-1));
        int yy = ty*RTH + (t >> 3);
        int o = (yy * W + xx) * 3;
        out[o + 0] = r;
        out[o + 1] = g;
        out[o + 2] = b;
    }
}

extern "C" void kernel_launch(void* const* d_in, const int* in_sizes, int n_in,
                              void* d_out, int out_size)
{
    const float* pos   = (const float*)d_in[0];
    const float* rgb   = (const float*)d_in[1];
    const float* opa   = (const float*)d_in[2];
    const float* quat  = (const float*)d_in[3];
    const float* scale = (const float*)d_in[4];
    const float* rot   = (const float*)d_in[5];
    const float* tran  = (const float*)d_in[6];
    float* out = (float*)d_out;

    static int smem_set = 0;
    if (!smem_set) {
        cudaFuncSetAttribute(render_kernel,
                             cudaFuncAttributeMaxDynamicSharedMemorySize,
                             RSMEM);
        smem_set = 1;
    }

    prepsort_kernel<<<PNB, PBT>>>(pos, rgb, opa, quat, scale, rot, tran);
    render_kernel<<<dim3(NTX, NTY), RBT, RSMEM>>>(out);
}